// round 6
// baseline (speedup 1.0000x reference)
#include <cuda_runtime.h>
#include <cuda_fp16.h>
#include <stdint.h>

#define TOKENS 16384
#define DIM    256
#define KW     8192

#define BM     128
#define BN     128
#define BK     64
#define SPLIT  8
#define NRANGE (KW / SPLIT)          // 1024 codes per CTA
#define NCHUNKS (NRANGE / BN)        // 8
#define KSTAGES (DIM / BK)           // 4 B-stages per chunk
#define GSTAGES (NCHUNKS * KSTAGES)  // 32

#define ROWA   528                    // A row stride bytes (512 data + 16 pad; 528%128==16)
#define A_BYTES (128 * ROWA)          // 67584
#define ROWB   144                    // B row stride bytes (128 data + 16 pad)
#define TILEB  (128 * ROWB)           // 18432
#define NBUF   5
#define B_OFF  A_BYTES
#define SMEM_BYTES (A_BYTES + NBUF * TILEB)   // 159744

#define MARGIN 0.1f

// ---------------- device scratch ----------------
__device__ float g_wn[KW];
__device__ float g_pval[TOKENS * SPLIT];
__device__ float g_pval2[TOKENS * SPLIT];
__device__ int   g_pidx[TOKENS * SPLIT];
__device__ int   g_flag[TOKENS];
__device__ __half g_xh[(size_t)TOKENS * DIM];
__device__ __half g_wh[(size_t)KW * DIM];

// ---------------- helpers ----------------
__device__ __forceinline__ uint32_t smem_u32(const void* p) {
    uint32_t a;
    asm("{ .reg .u64 t; cvta.to.shared.u64 t, %1; cvt.u32.u64 %0, t; }" : "=r"(a) : "l"(p));
    return a;
}

#define CP_ASYNC16(dst, src) \
    asm volatile("cp.async.cg.shared.global [%0], [%1], 16;" :: "r"(dst), "l"(src) : "memory")

#define LDSM_X4(r0, r1, r2, r3, addr) \
    asm volatile("ldmatrix.sync.aligned.m8n8.x4.shared.b16 {%0,%1,%2,%3}, [%4];" \
                 : "=r"(r0), "=r"(r1), "=r"(r2), "=r"(r3) : "r"(addr))

#define MMA_F16(c, a0, a1, a2, a3, b0, b1) \
    asm volatile("mma.sync.aligned.m16n8k16.row.col.f32.f16.f16.f32 " \
                 "{%0,%1,%2,%3}, {%4,%5,%6,%7}, {%8,%9}, {%0,%1,%2,%3};" \
                 : "+f"((c)[0]), "+f"((c)[1]), "+f"((c)[2]), "+f"((c)[3]) \
                 : "r"(a0), "r"(a1), "r"(a2), "r"(a3), "r"(b0), "r"(b1))

__device__ __forceinline__ void top2_ins(float s, int n, float& v1, int& i1, float& v2) {
    if (s > v1 || (s == v1 && n < i1)) { v2 = v1; v1 = s; i1 = n; }
    else if (s > v2) v2 = s;
}
__device__ __forceinline__ void top2_mrg(float ov1, int oi1, float ov2,
                                         float& v1, int& i1, float& v2) {
    if (ov1 > v1 || (ov1 == v1 && oi1 < i1)) { v2 = fmaxf(v1, ov2); v1 = ov1; i1 = oi1; }
    else v2 = fmaxf(v2, ov1);
}

// ---------------- prepass: fp16 convert (x & w) + w row norms ----------------
// blocks [0, 1024): x convert (float4/thread). blocks [1024, 1056): w rows (row/thread).
__global__ void prepass_kernel(const float* __restrict__ x, const float* __restrict__ w) {
    const int b = blockIdx.x;
    if (b < TOKENS * DIM / 4 / 256) {
        const int i = b * 256 + threadIdx.x;
        const float4 v = ((const float4*)x)[i];
        ((__half2*)g_xh)[i * 2]     = __floats2half2_rn(v.x, v.y);
        ((__half2*)g_xh)[i * 2 + 1] = __floats2half2_rn(v.z, v.w);
    } else {
        const int row = (b - TOKENS * DIM / 4 / 256) * 256 + threadIdx.x;  // 0..8191
        const float4* src = (const float4*)(w + (size_t)row * DIM);
        __half2* dst = (__half2*)(g_wh + (size_t)row * DIM);
        float s = 0.f;
#pragma unroll
        for (int c = 0; c < DIM / 4; c++) {
            const float4 v = __ldg(src + c);
            s += v.x * v.x + v.y * v.y + v.z * v.z + v.w * v.w;
            dst[c * 2]     = __floats2half2_rn(v.x, v.y);
            dst[c * 2 + 1] = __floats2half2_rn(v.z, v.w);
        }
        g_wn[row] = s;
    }
}

// ---------------- main kernel ----------------
extern __shared__ char dynsmem[];

__device__ __forceinline__ void prefetch_B(uint32_t sbase, int gs, int tid, int nbase0) {
    if (gs < GSTAGES) {
        const int buf = gs % NBUF;
        const int nb = nbase0 + (gs >> 2) * BN;
        const int kb = (gs & 3) * BK;
        const uint32_t base = sbase + B_OFF + buf * TILEB;
#pragma unroll
        for (int i = 0; i < 4; i++) {
            const int f = tid + 256 * i;
            const int row = f >> 3, c16 = f & 7;
            CP_ASYNC16(base + row * ROWB + c16 * 16,
                       g_wh + (size_t)(nb + row) * DIM + kb + c16 * 8);
        }
    }
    asm volatile("cp.async.commit_group;" ::: "memory");
}

__global__ __launch_bounds__(256, 1)
void vq_mma_kernel() {
    char* sm = dynsmem;
    const uint32_t sbase = smem_u32(sm);
    const int tid = threadIdx.x;
    const int lane = tid & 31;
    const int wid = tid >> 5;
    const int warp_m = wid >> 2;      // 0..1
    const int warp_n = wid & 3;       // 0..3
    const int mbase = blockIdx.x * BM;
    const int nbase0 = blockIdx.y * NRANGE;

    // ---- load A (x tile) once: 128 rows x 512 bytes ----
    {
#pragma unroll
        for (int i = 0; i < 16; i++) {
            const int f = tid + 256 * i;
            const int row = f >> 5, c16 = f & 31;
            CP_ASYNC16(sbase + row * ROWA + c16 * 16,
                       g_xh + (size_t)(mbase + row) * DIM + c16 * 8);
        }
        asm volatile("cp.async.commit_group;" ::: "memory");
    }
    // ---- prime B pipeline: stages 0..3 ----
    prefetch_B(sbase, 0, tid, nbase0);
    prefetch_B(sbase, 1, tid, nbase0);
    prefetch_B(sbase, 2, tid, nbase0);
    prefetch_B(sbase, 3, tid, nbase0);
    asm volatile("cp.async.wait_group 4;" ::: "memory");   // A ready
    __syncthreads();

    const uint32_t aOff = (uint32_t)(warp_m * 64 + ((lane >> 3) & 1) * 8 + (lane & 7)) * ROWA
                        + ((lane >> 4) & 1) * 16;
    const uint32_t bOff = (uint32_t)(warp_n * 32 + ((lane >> 4) & 1) * 8 + (lane & 7)) * ROWB
                        + ((lane >> 3) & 1) * 16;

    float acc[4][4][4];
#pragma unroll
    for (int f = 0; f < 4; f++)
#pragma unroll
        for (int j = 0; j < 4; j++)
#pragma unroll
            for (int e = 0; e < 4; e++) acc[f][j][e] = 0.f;

    float bv[8], bv2[8];
    int   bi[8];
#pragma unroll
    for (int s = 0; s < 8; s++) { bv[s] = -3.402823e38f; bv2[s] = -3.402823e38f; bi[s] = 0x7fffffff; }

    for (int gs = 0; gs < GSTAGES; gs++) {
        prefetch_B(sbase, gs + 4, tid, nbase0);            // always commits (maybe empty)
        asm volatile("cp.async.wait_group 4;" ::: "memory"); // stage gs ready
        __syncthreads();

        const uint32_t bbase = sbase + B_OFF + (gs % NBUF) * TILEB;
        const int kb16 = (gs & 3) * 4;                     // k16 index base within DIM

#pragma unroll
        for (int k = 0; k < BK / 16; k++) {
            uint32_t a[4][4];
#pragma unroll
            for (int f = 0; f < 4; f++)
                LDSM_X4(a[f][0], a[f][1], a[f][2], a[f][3],
                        sbase + aOff + f * 16 * ROWA + (kb16 + k) * 32);
            uint32_t b[8];
            LDSM_X4(b[0], b[1], b[2], b[3], bbase + bOff + k * 32);
            LDSM_X4(b[4], b[5], b[6], b[7], bbase + bOff + 16 * ROWB + k * 32);
#pragma unroll
            for (int f = 0; f < 4; f++)
#pragma unroll
                for (int j = 0; j < 4; j++)
                    MMA_F16(acc[f][j], a[f][0], a[f][1], a[f][2], a[f][3],
                            b[2 * j], b[2 * j + 1]);
        }
        __syncthreads();   // B buffer consumed before producer overwrites (depth < NBUF keeps this cheap)

        if ((gs & 3) == 3) {
            const int nb = nbase0 + (gs >> 2) * BN;
#pragma unroll
            for (int f = 0; f < 4; f++) {
#pragma unroll
                for (int j = 0; j < 4; j++) {
                    const int n0 = nb + warp_n * 32 + j * 8 + (lane & 3) * 2;
                    const float wn0 = __ldg(&g_wn[n0]);
                    const float wn1 = __ldg(&g_wn[n0 + 1]);
                    const float s00 = wn0 - 2.f * acc[f][j][0];
                    const float s01 = wn1 - 2.f * acc[f][j][1];
                    const float s10 = wn0 - 2.f * acc[f][j][2];
                    const float s11 = wn1 - 2.f * acc[f][j][3];
                    const int t0 = 2 * f, t1 = 2 * f + 1;
                    top2_ins(s00, n0,     bv[t0], bi[t0], bv2[t0]);
                    top2_ins(s01, n0 + 1, bv[t0], bi[t0], bv2[t0]);
                    top2_ins(s10, n0,     bv[t1], bi[t1], bv2[t1]);
                    top2_ins(s11, n0 + 1, bv[t1], bi[t1], bv2[t1]);
                    acc[f][j][0] = 0.f; acc[f][j][1] = 0.f;
                    acc[f][j][2] = 0.f; acc[f][j][3] = 0.f;
                }
            }
        }
    }

#pragma unroll
    for (int off = 1; off <= 2; off <<= 1) {
#pragma unroll
        for (int s = 0; s < 8; s++) {
            float ov1 = __shfl_xor_sync(0xffffffffu, bv[s], off);
            int   oi1 = __shfl_xor_sync(0xffffffffu, bi[s], off);
            float ov2 = __shfl_xor_sync(0xffffffffu, bv2[s], off);
            top2_mrg(ov1, oi1, ov2, bv[s], bi[s], bv2[s]);
        }
    }

    __syncthreads();
    float* red_val  = (float*)sm;
    int*   red_idx  = (int*)(sm + 2048);
    float* red_val2 = (float*)(sm + 4096);

    if ((lane & 3) == 0) {
        const int g = lane >> 2;
#pragma unroll
        for (int s = 0; s < 8; s++) {
            const int row = warp_m * 64 + (s >> 1) * 16 + (s & 1) * 8 + g;
            red_val[row * 4 + warp_n]  = bv[s];
            red_idx[row * 4 + warp_n]  = bi[s];
            red_val2[row * 4 + warp_n] = bv2[s];
        }
    }
    __syncthreads();

    if (tid < BM) {
        float v1 = -3.402823e38f, v2 = -3.402823e38f;
        int   i1 = 0x7fffffff;
#pragma unroll
        for (int wn = 0; wn < 4; wn++)
            top2_mrg(red_val[tid * 4 + wn], red_idx[tid * 4 + wn],
                     red_val2[tid * 4 + wn], v1, i1, v2);
        const int tok = mbase + tid;
        g_pval[tok * SPLIT + blockIdx.y]  = v1;
        g_pidx[tok * SPLIT + blockIdx.y]  = i1;
        g_pval2[tok * SPLIT + blockIdx.y] = v2;
    }
}

// ---------------- combine split partials + flag + gather ----------------
__global__ void reduce_gather_kernel(const float* __restrict__ wt, float* __restrict__ out) {
    const int tok = blockIdx.x;
    float v1 = -3.402823e38f, v2 = -3.402823e38f;
    int   i1 = 0x7fffffff;
#pragma unroll
    for (int s = 0; s < SPLIT; s++)
        top2_mrg(g_pval[tok * SPLIT + s], g_pidx[tok * SPLIT + s],
                 g_pval2[tok * SPLIT + s], v1, i1, v2);
    const int flag = (v1 - v2 < MARGIN) ? 1 : 0;
    if (threadIdx.x == 0) g_flag[tok] = flag;
    if (!flag) {
        const float4 v = *(const float4*)(wt + (size_t)i1 * DIM + threadIdx.x * 4);
        *(float4*)(out + (size_t)tok * DIM + threadIdx.x * 4) = v;
    }
}

// ---------------- exact fp32 rescue for flagged tokens ----------------
__global__ __launch_bounds__(256)
void rescue_kernel(const float* __restrict__ x, const float* __restrict__ wt,
                   float* __restrict__ out) {
    const int tok = blockIdx.x;
    if (!g_flag[tok]) return;

    __shared__ float xs[DIM];
    __shared__ float rv[8];
    __shared__ int   ri[8];
    __shared__ int   widx;

    const int tid = threadIdx.x;
    if (tid < DIM / 4)
        *(float4*)(xs + tid * 4) = *(const float4*)(x + (size_t)tok * DIM + tid * 4);
    __syncthreads();

    float bv = -3.402823e38f;
    int   bi = 0x7fffffff;
    for (int n = tid; n < KW; n += 256) {
        const float* wr = wt + (size_t)n * DIM;
        float d = 0.f;
#pragma unroll
        for (int c = 0; c < DIM / 4; c++) {
            const float4 wv = __ldg((const float4*)(wr + c * 4));
            const float4 xv = *(const float4*)(xs + c * 4);
            d += xv.x * wv.x + xv.y * wv.y + xv.z * wv.z + xv.w * wv.w;
        }
        const float sc = __ldg(&g_wn[n]) - 2.f * d;
        if (sc > bv || (sc == bv && n < bi)) { bv = sc; bi = n; }
    }
#pragma unroll
    for (int off = 16; off >= 1; off >>= 1) {
        float ov = __shfl_xor_sync(0xffffffffu, bv, off);
        int   oi = __shfl_xor_sync(0xffffffffu, bi, off);
        if (ov > bv || (ov == bv && oi < bi)) { bv = ov; bi = oi; }
    }
    if ((tid & 31) == 0) { rv[tid >> 5] = bv; ri[tid >> 5] = bi; }
    __syncthreads();
    if (tid == 0) {
        float v = rv[0]; int i = ri[0];
#pragma unroll
        for (int wgi = 1; wgi < 8; wgi++) {
            if (rv[wgi] > v || (rv[wgi] == v && ri[wgi] < i)) { v = rv[wgi]; i = ri[wgi]; }
        }
        widx = i;
    }
    __syncthreads();
    const int sel = widx;
    if (tid < DIM / 4) {
        const float4 v = *(const float4*)(wt + (size_t)sel * DIM + tid * 4);
        *(float4*)(out + (size_t)tok * DIM + tid * 4) = v;
    }
}

// ---------------- launch ----------------
extern "C" void kernel_launch(void* const* d_in, const int* in_sizes, int n_in,
                              void* d_out, int out_size) {
    const float* x  = (const float*)d_in[0];   // [16384, 256]
    const float* wt = (const float*)d_in[1];   // [8192, 256]
    float* out = (float*)d_out;

    cudaFuncSetAttribute(vq_mma_kernel, cudaFuncAttributeMaxDynamicSharedMemorySize, SMEM_BYTES);

    prepass_kernel<<<TOKENS * DIM / 4 / 256 + KW / 256, 256>>>(x, wt);

    dim3 grid(TOKENS / BM, SPLIT);
    vq_mma_kernel<<<grid, 256, SMEM_BYTES>>>();

    reduce_gather_kernel<<<TOKENS, 64>>>(wt, out);
    rescue_kernel<<<TOKENS, 256>>>(x, wt, out);
}